// round 7
// baseline (speedup 1.0000x reference)
#include <cuda_runtime.h>
#include <cuda_fp16.h>
#include <mma.h>
#include <cstdint>

using namespace nvcuda;

#define NODES_MAX 50000
#define DDIM 256          // input feature dim
#define ADIM 128          // attention dim (q or k width)
#define QKW 256           // concat width: [q | k]

// fp16 scratch tables
__device__ __half g_qk[(size_t)NODES_MAX * QKW];   // output of GEMM: [q|k] per node
__device__ __half g_xh[(size_t)NODES_MAX * DDIM];  // fp16 copy of x
__device__ __half g_wh[(size_t)QKW * DDIM];        // fp16 [Wq ; Wk]

// ---------------------------------------------------------------------------
// Kernel 0: fp32 -> fp16 convert for x and W (pure streaming)
// ---------------------------------------------------------------------------
__global__ __launch_bounds__(256)
void convert_kernel(const float* __restrict__ x,
                    const float* __restrict__ Wq,
                    const float* __restrict__ Wk,
                    int nx4, int nw4h)   // nx4 = N*64, nw4h = float4 count of one W
{
    int i = blockIdx.x * blockDim.x + threadIdx.x;
    const int total = nx4 + 2 * nw4h;
    if (i >= total) return;
    float4 v;
    __half* dst;
    if (i < nx4) {
        v = reinterpret_cast<const float4*>(x)[i];
        dst = g_xh + (size_t)i * 4;
    } else {
        int w = i - nx4;
        v = (w < nw4h) ? reinterpret_cast<const float4*>(Wq)[w]
                       : reinterpret_cast<const float4*>(Wk)[w - nw4h];
        dst = g_wh + (size_t)w * 4;
    }
    __half2 h0 = __floats2half2_rn(v.x, v.y);
    __half2 h1 = __floats2half2_rn(v.z, v.w);
    uint2 pk;
    pk.x = *reinterpret_cast<unsigned int*>(&h0);
    pk.y = *reinterpret_cast<unsigned int*>(&h1);
    *reinterpret_cast<uint2*>(dst) = pk;
}

// ---------------------------------------------------------------------------
// cp.async helpers (16B, L2-cached, zero-fill on predicate false)
// ---------------------------------------------------------------------------
__device__ __forceinline__ void cp16(void* dst, const void* src, bool pred) {
    unsigned sa = (unsigned)__cvta_generic_to_shared(dst);
    int sz = pred ? 16 : 0;
    asm volatile("cp.async.cg.shared.global [%0], [%1], 16, %2;\n"
                 :: "r"(sa), "l"(src), "r"(sz));
}
__device__ __forceinline__ void cp_commit() {
    asm volatile("cp.async.commit_group;\n");
}
template <int W>
__device__ __forceinline__ void cp_wait() {
    asm volatile("cp.async.wait_group %0;\n" :: "n"(W));
}

// ---------------------------------------------------------------------------
// Kernel 1: projection GEMM, fp16 inputs, 3-stage cp.async pipeline.
//   qk[n][j] = sum_d xh[n][d] * wh[j][d] + b[j]
// BM=64, BN=128, BK=32, 256 threads (8 warps, 2m x 4n), warp tile 32x32.
// One __syncthreads per iter: commit at iter k writes buf (k+2)%3, which was
// last read at iter k-1 and is protected by the top-of-iter sync.
// Last iteration uses wait<0> (all groups committed by then; wait<1> would
// allow the newest group -- this iteration's data -- to still be in flight).
// ---------------------------------------------------------------------------
#define KITERS (DDIM / 32)    // 8

__global__ __launch_bounds__(256)
void gemm_qk_cp(const float* __restrict__ bq,
                const float* __restrict__ bk,
                int N)
{
    __shared__ __align__(16) __half As[3][64][40];    // [stage][m][k]
    __shared__ __align__(16) __half Bs[3][128][40];   // [stage][n][k]

    const int tid  = threadIdx.x;
    const int wid  = tid >> 5;
    const int lane = tid & 31;
    const int m0   = blockIdx.x * 64;
    const int n0   = blockIdx.y * 128;

    const int wm = wid & 1;           // m offset wm*32
    const int wn = wid >> 1;          // n offset wn*32

    wmma::fragment<wmma::accumulator, 16, 16, 16, float> c[2][2];
    #pragma unroll
    for (int i = 0; i < 2; i++)
        #pragma unroll
        for (int j = 0; j < 2; j++)
            wmma::fill_fragment(c[i][j], 0.0f);

    // A: 64 rows x 4 16B-chunks = 256 chunks -> 1/thread
    const int arow = tid >> 2;
    const int acol = (tid & 3) * 8;           // halves
    // B: 128 rows x 4 chunks = 512 -> 2/thread
    const int brow = tid >> 1;
    const int bcol = (tid & 1) * 16;          // halves (+0, +8)

    const int gm   = m0 + arow;
    const bool mok = gm < N;
    const __half* asrc = g_xh + (size_t)gm * DDIM + acol;
    const __half* bsrc = g_wh + (size_t)(n0 + brow) * DDIM + bcol;

    // prologue: stages 0, 1
    #pragma unroll
    for (int s = 0; s < 2; s++) {
        const int k0 = s * 32;
        cp16(&As[s][arow][acol],     asrc + k0,     mok);
        cp16(&Bs[s][brow][bcol],     bsrc + k0,     true);
        cp16(&Bs[s][brow][bcol + 8], bsrc + k0 + 8, true);
        cp_commit();
    }

    #pragma unroll
    for (int it = 0; it < KITERS; it++) {
        const int buf = it % 3;
        if (it == KITERS - 1) cp_wait<0>(); else cp_wait<1>();
        __syncthreads();

        // issue loads for iter it+2 into buf (it+2)%3 (read at iter it-1, safe)
        const int kn = (it + 2) * 32;
        if (kn < DDIM) {
            const int nbuf = (it + 2) % 3;
            cp16(&As[nbuf][arow][acol],     asrc + kn,     mok);
            cp16(&Bs[nbuf][brow][bcol],     bsrc + kn,     true);
            cp16(&Bs[nbuf][brow][bcol + 8], bsrc + kn + 8, true);
            cp_commit();
        }

        #pragma unroll
        for (int ks = 0; ks < 32; ks += 16) {
            wmma::fragment<wmma::matrix_a, 16, 16, 16, __half, wmma::row_major> a[2];
            wmma::fragment<wmma::matrix_b, 16, 16, 16, __half, wmma::col_major> b[2];
            #pragma unroll
            for (int i = 0; i < 2; i++)
                wmma::load_matrix_sync(a[i], &As[buf][wm * 32 + i * 16][ks], 40);
            #pragma unroll
            for (int j = 0; j < 2; j++)
                wmma::load_matrix_sync(b[j], &Bs[buf][wn * 32 + j * 16][ks], 40);
            #pragma unroll
            for (int i = 0; i < 2; i++)
                #pragma unroll
                for (int j = 0; j < 2; j++)
                    wmma::mma_sync(c[i][j], a[i], b[j], c[i][j]);
        }
    }
    __syncthreads();   // all reads done before epilogue trashes Bs

    // epilogue: alias per-warp f32 staging onto Bs
    float* epw = reinterpret_cast<float*>(&Bs[0][0][0]) + wid * 256;
    const int erow = lane & 15;
    const int ecg  = (lane >> 4) * 8;
    #pragma unroll
    for (int i = 0; i < 2; i++) {
        #pragma unroll
        for (int j = 0; j < 2; j++) {
            wmma::store_matrix_sync(epw, c[i][j], 16, wmma::mem_row_major);
            __syncwarp();
            int gmm = m0 + wm * 32 + i * 16 + erow;
            int gj0 = n0 + wn * 32 + j * 16 + ecg;
            if (gmm < N) {
                __half hv[8];
                #pragma unroll
                for (int t = 0; t < 8; t++) {
                    int gj = gj0 + t;
                    float bias = (gj < ADIM) ? bq[gj] : bk[gj - ADIM];
                    hv[t] = __float2half(epw[erow * 16 + ecg + t] + bias);
                }
                *reinterpret_cast<uint4*>(g_qk + (size_t)gmm * QKW + gj0) =
                    *reinterpret_cast<const uint4*>(hv);
            }
            __syncwarp();
        }
    }
}

// ---------------------------------------------------------------------------
// Kernel 2: per-edge symmetric attention score + fused scatter-add.
// 8 lanes per edge, 4 edges per warp.
// ---------------------------------------------------------------------------
__global__ __launch_bounds__(256)
void edge_kernel(const int* __restrict__ ei,     // [2, E]
                 const int* __restrict__ d0r1,   // d0_index row 1, [2E]
                 float* __restrict__ out,
                 int N, int E)
{
    const int warp = (blockIdx.x * blockDim.x + threadIdx.x) >> 5;
    const int lane = threadIdx.x & 31;
    const int g    = lane >> 3;          // edge group within warp, 0..3
    const int l    = lane & 7;           // lane within group
    const int e    = warp * 4 + g;
    if (e >= E) return;

    const int s = __ldg(ei + e);
    const int d = __ldg(ei + E + e);

    const uint4* rs = reinterpret_cast<const uint4*>(g_qk + (size_t)s * QKW);
    const uint4* rd = reinterpret_cast<const uint4*>(g_qk + (size_t)d * QKW);

    const uint4 a0 = rs[l];        const uint4 b0 = rd[16 + l];   // q_s . k_d (lo)
    const uint4 a1 = rs[8 + l];    const uint4 b1 = rd[24 + l];   // q_s . k_d (hi)
    const uint4 a2 = rd[l];        const uint4 b2 = rs[16 + l];   // q_d . k_s (lo)
    const uint4 a3 = rd[8 + l];    const uint4 b3 = rs[24 + l];   // q_d . k_s (hi)

    float p = 0.f;
    {
        const __half2* ah; const __half2* bh;
        #define DOT8(AV, BV)                                         \
            ah = reinterpret_cast<const __half2*>(&(AV));            \
            bh = reinterpret_cast<const __half2*>(&(BV));            \
            _Pragma("unroll")                                        \
            for (int i = 0; i < 4; i++) {                            \
                float2 fa = __half22float2(ah[i]);                   \
                float2 fb = __half22float2(bh[i]);                   \
                p = fmaf(fa.x, fb.x, p);                             \
                p = fmaf(fa.y, fb.y, p);                             \
            }
        DOT8(a0, b0)
        DOT8(a1, b1)
        DOT8(a2, b2)
        DOT8(a3, b3)
        #undef DOT8
    }

    p += __shfl_xor_sync(0xffffffffu, p, 4);
    p += __shfl_xor_sync(0xffffffffu, p, 2);
    p += __shfl_xor_sync(0xffffffffu, p, 1);

    if (l == 0) {
        const float v = __expf(p * 0.0625f);   // (0.5/8) * sum
        out[N + e] = v;                        // diagA1
        int2 dp = *reinterpret_cast<const int2*>(d0r1 + 2 * e);
        atomicAdd(out + dp.x, v);              // diagA0 scatter (no return -> RED)
        atomicAdd(out + dp.y, v);
    }
}

// ---------------------------------------------------------------------------
extern "C" void kernel_launch(void* const* d_in, const int* in_sizes, int n_in,
                              void* d_out, int out_size)
{
    const float* x  = (const float*)d_in[0];
    const float* Wq = (const float*)d_in[1];
    const float* bq = (const float*)d_in[2];
    const float* Wk = (const float*)d_in[3];
    const float* bk = (const float*)d_in[4];
    const int*   ei = (const int*)d_in[5];
    const int*   d0 = (const int*)d_in[6];
    float* out = (float*)d_out;

    const int A    = in_sizes[2];             // 128
    const int Dd   = in_sizes[1] / A;         // 256
    const int N    = in_sizes[0] / Dd;        // 50000
    const int E    = in_sizes[5] / 2;         // 800000
    const int twoE = in_sizes[6] / 2;         // 2E (row stride of d0_index)
    (void)n_in; (void)out_size;

    cudaMemsetAsync(out, 0, (size_t)N * sizeof(float), 0);

    // fp32 -> fp16 tables (one element chunk per thread)
    const int nx4  = N * (Dd / 4);
    const int nw4h = A * Dd / 4;
    int cblocks = (nx4 + 2 * nw4h + 255) / 256;
    convert_kernel<<<cblocks, 256>>>(x, Wq, Wk, nx4, nw4h);

    // projection GEMM: BM=64, BN=128
    dim3 ggrd((N + 63) / 64, QKW / 128);
    gemm_qk_cp<<<ggrd, 256>>>(bq, bk, N);

    // per-edge score + scatter: 4 edges per warp, 8 warps per block
    int nwarps = (E + 3) / 4;
    int blocks = (nwarps + 7) / 8;
    edge_kernel<<<blocks, 256>>>(ei, d0 + twoE, out, N, E);
}